// round 6
// baseline (speedup 1.0000x reference)
#include <cuda_runtime.h>
#include <cuda_fp16.h>
#include <cstdint>
#include <cstddef>

// Problem constants
#define Bz 32
#define Sz 2048
#define Hz 1024
#define Uz 1024
#define MTOT 65536   // B*S

// Scratch (device globals — no runtime allocation)
__device__ __align__(128) __half g_W1h[Uz * Hz];          // W1^T: [u][h] fp16
__device__ __align__(128) __half g_Xh[(size_t)MTOT * Hz]; // X fp16: [m][h]
__device__ float g_ph[Bz * Uz];                            // W1_b + W2_b + h @ W2
__device__ float g_score[MTOT];                            // pre-softmax scores

// ---------------- PTX helpers (baseline compute_103 only) ----------------
__device__ __forceinline__ uint32_t smem_u32(const void* p) {
    uint32_t a;
    asm("{ .reg .u64 t; cvta.to.shared.u64 t, %1; cvt.u32.u64 %0, t; }" : "=r"(a) : "l"(p));
    return a;
}

#define LDSM_X4(r0, r1, r2, r3, addr)                                        \
    asm volatile("ldmatrix.sync.aligned.m8n8.x4.shared.b16 {%0,%1,%2,%3}, [%4];" \
        : "=r"(r0), "=r"(r1), "=r"(r2), "=r"(r3) : "r"(addr))

#define MMA16816(c, a, b0v, b1v)                                             \
    asm volatile("mma.sync.aligned.m16n8k16.row.col.f32.f16.f16.f32 "        \
        "{%0,%1,%2,%3}, {%4,%5,%6,%7}, {%8,%9}, {%0,%1,%2,%3};"              \
        : "+f"((c)[0]), "+f"((c)[1]), "+f"((c)[2]), "+f"((c)[3])             \
        : "r"((a)[0]), "r"((a)[1]), "r"((a)[2]), "r"((a)[3]),                \
          "r"(b0v), "r"(b1v))

__device__ __forceinline__ uint32_t sw128(uint32_t off) {
    return off ^ ((off >> 3) & 0x70);
}

// fast accurate-enough tanh
__device__ __forceinline__ float tanh_fast(float x) {
    x = fminf(fmaxf(x, -15.f), 15.f);
    float e = __expf(2.f * x);
    return __fdividef(e - 1.f, e + 1.f);
}

// ---------------- prep kernels ----------------
// X fp32 -> fp16 streaming convert (row layout preserved)
__global__ void __launch_bounds__(256)
k_convert_x(const float* __restrict__ X) {
    size_t i = (size_t)blockIdx.x * 256 + threadIdx.x;   // float4 index
    const size_t stride = (size_t)gridDim.x * 256;
    const size_t total = (size_t)MTOT * Hz / 4;
    for (; i < total; i += stride) {
        float4 v = *reinterpret_cast<const float4*>(X + i * 4);
        __half2 h0 = __floats2half2_rn(v.x, v.y);
        __half2 h1 = __floats2half2_rn(v.z, v.w);
        uint2 pk = make_uint2(*reinterpret_cast<uint32_t*>(&h0),
                              *reinterpret_cast<uint32_t*>(&h1));
        *reinterpret_cast<uint2*>(g_Xh + i * 4) = pk;
    }
}

// Transpose + convert W1 [H,U] fp32 -> g_W1h [U,H] fp16
__global__ void k_convert_w1(const float* __restrict__ W1) {
    __shared__ float t[32][33];
    int u0 = blockIdx.x * 32, h0 = blockIdx.y * 32;
    int tx = threadIdx.x, ty = threadIdx.y;  // 32 x 8
    #pragma unroll
    for (int j = 0; j < 32; j += 8)
        t[ty + j][tx] = W1[(size_t)(h0 + ty + j) * Uz + u0 + tx];
    __syncthreads();
    #pragma unroll
    for (int j = 0; j < 32; j += 8)
        g_W1h[(size_t)(u0 + ty + j) * Hz + h0 + tx] = __float2half(t[tx][ty + j]);
}

// ph[b][u] = W1_b[u] + W2_b[u]; also zero g_score
__global__ void k_init_ph(const float* __restrict__ W1b, const float* __restrict__ W2b) {
    int i = blockIdx.x * 256 + threadIdx.x;  // 32768 total
    int u = i & (Uz - 1);
    g_ph[i] = W1b[u] + W2b[u];
    g_score[i] = 0.f;
    g_score[i + 32768] = 0.f;
}

// ph[b][u] += sum_h lh[b][h] * W2[h][u]   (h-slices of 32 for grid width)
__global__ void k_ph(const float* __restrict__ lh, const float* __restrict__ W2) {
    __shared__ float lh_s[32][32];
    int u0 = blockIdx.x * 128, h0 = blockIdx.y * 32;
    int tid = threadIdx.x;
    for (int idx = tid; idx < 1024; idx += 256) {
        int bb = idx >> 5, hh = idx & 31;
        lh_s[bb][hh] = lh[bb * Hz + h0 + hh];
    }
    __syncthreads();
    int u = u0 + (tid & 127);
    int bh = (tid >> 7) * 16;
    float acc[16];
    #pragma unroll
    for (int i = 0; i < 16; ++i) acc[i] = 0.f;
    for (int hh = 0; hh < 32; ++hh) {
        float w = W2[(size_t)(h0 + hh) * Uz + u];
        #pragma unroll
        for (int i = 0; i < 16; ++i) acc[i] += lh_s[bh + i][hh] * w;
    }
    #pragma unroll
    for (int i = 0; i < 16; ++i) atomicAdd(&g_ph[(bh + i) * Uz + u], acc[i]);
}

// ---------------- fused main: GEMM(HMMA) + tanh + V-dot ----------------
// Grid (512, 2): M-tile 128 rows, N-half of 512 cols (4 chunks of 128).
// 512 threads / 16 warps (4 per SMSP), warp tile 32(m) x 32(n) in a 4x4 warp
// grid. K streamed in 16 slices of 64 via a 4-stage cp.async pipeline.
// SMEM map (bytes):
//   [0   .. 512)    score_s (128 f32)
//   [512 .. 1024)   ph_s    (128 f32)
//   [1024.. 1536)   v_s     (128 f32)
//   [2048.. 67584)  X fp16  4 stages x [128 x 64] SW128
//   [67584..133120) W fp16  4 stages x [128 x 64] SW128
#define SMEM_MAIN 133120

__global__ void __launch_bounds__(512, 1)
k_main(const float* __restrict__ Vw) {
    extern __shared__ char smem[];
    const uint32_t sb = smem_u32(smem);
    float* score_s = reinterpret_cast<float*>(smem);
    float* ph_s = reinterpret_cast<float*>(smem + 512);
    float* v_s = reinterpret_cast<float*>(smem + 1024);
    const uint32_t XS = sb + 2048;
    const uint32_t WS = sb + 67584;

    const int tid = threadIdx.x;
    const int wid = tid >> 5, l = tid & 31;
    const int wm = wid & 3, wn = wid >> 2;     // 4 x 4 warp grid
    const int m0 = blockIdx.x * 128;
    const int nh = blockIdx.y;                 // n-half (0 or 1)
    const int b = m0 >> 11;                    // batch (2048 rows each)

    if (tid < 128) score_s[tid] = 0.f;

    // ldmatrix lane-invariant offset pieces
    const uint32_t a_row = (uint32_t)(wm * 32 + (l & 15));
    const uint32_t a_k16 = (uint32_t)(((l >> 4) & 1) * 16);
    const uint32_t b_row = (uint32_t)(wn * 32 + ((l >> 4) & 1) * 8 + (l & 7));
    const uint32_t b_k16 = (uint32_t)(((l >> 3) & 1) * 16);

    // cp.async pieces: 1024 16B chunks per 128x64 tile, 512 threads -> 2 each
    const int cp_r = tid >> 3;            // row 0..63
    const int cp_c = tid & 7;             // 16B column 0..7

    for (int nc = 0; nc < 4; ++nc) {
        const int n0 = nh * 512 + nc * 128;    // global n offset of this chunk
        if (tid < 128) {
            ph_s[tid] = g_ph[b * Uz + n0 + tid];
            v_s[tid] = Vw[n0 + tid];
        }

        float acc[2][4][4];
        #pragma unroll
        for (int mb = 0; mb < 2; ++mb)
            #pragma unroll
            for (int nb = 0; nb < 4; ++nb)
                #pragma unroll
                for (int i = 0; i < 4; ++i) acc[mb][nb][i] = 0.f;

        // ---- issue cp.async loads for slice s into stage s&3 ----
        auto load_slice = [&](int s) {
            const int st = s & 3;
            const int k0 = s * 64;
            const uint32_t wdst = WS + st * 16384;
            const uint32_t xdst = XS + st * 16384;
            const __half* wsrc = g_W1h + (size_t)n0 * Hz + k0;
            const __half* xsrc = g_Xh + (size_t)m0 * Hz + k0;
            #pragma unroll
            for (int i = 0; i < 2; ++i) {
                int r = cp_r + i * 64;
                uint32_t dso = sw128((uint32_t)(r * 128 + cp_c * 16));
                size_t gw = __cvta_generic_to_global(wsrc + (size_t)r * Hz + cp_c * 8);
                size_t gx = __cvta_generic_to_global(xsrc + (size_t)r * Hz + cp_c * 8);
                asm volatile("cp.async.cg.shared.global [%0], [%1], 16;"
                             :: "r"(wdst + dso), "l"(gw));
                asm volatile("cp.async.cg.shared.global [%0], [%1], 16;"
                             :: "r"(xdst + dso), "l"(gx));
            }
            asm volatile("cp.async.commit_group;");
        };

        // prologue: fill 3 stages
        load_slice(0);
        load_slice(1);
        load_slice(2);

        for (int s = 0; s < 16; ++s) {
            if (s < 14)      asm volatile("cp.async.wait_group 2;");
            else if (s < 15) asm volatile("cp.async.wait_group 1;");
            else             asm volatile("cp.async.wait_group 0;");
            __syncthreads();   // publish stage s; stage (s+3)&3 free

            if (s + 3 < 16) load_slice(s + 3);

            const uint32_t xb = XS + (s & 3) * 16384;
            const uint32_t wb = WS + (s & 3) * 16384;

            #pragma unroll
            for (int kk = 0; kk < 4; ++kk) {
                uint32_t fa[2][4], fb[2][4];
                #pragma unroll
                for (int mb = 0; mb < 2; ++mb) {
                    uint32_t off = (a_row + mb * 16) * 128 + kk * 32 + a_k16;
                    LDSM_X4(fa[mb][0], fa[mb][1], fa[mb][2], fa[mb][3],
                            xb + sw128(off));
                }
                #pragma unroll
                for (int p = 0; p < 2; ++p) {
                    uint32_t off = (b_row + p * 16) * 128 + kk * 32 + b_k16;
                    LDSM_X4(fb[p][0], fb[p][1], fb[p][2], fb[p][3],
                            wb + sw128(off));
                }
                #pragma unroll
                for (int mb = 0; mb < 2; ++mb)
                    #pragma unroll
                    for (int nb = 0; nb < 4; ++nb)
                        MMA16816(acc[mb][nb], fa[mb],
                                 fb[nb >> 1][(nb & 1) * 2],
                                 fb[nb >> 1][(nb & 1) * 2 + 1]);
            }
        }

        // ---- epilogue for this n-chunk: tanh(acc + ph) * v, reduce over n ----
        const int t = l & 3, g = l >> 2;
        float rs[4] = {0.f, 0.f, 0.f, 0.f};
        #pragma unroll
        for (int mb = 0; mb < 2; ++mb) {
            #pragma unroll
            for (int nb = 0; nb < 4; ++nb) {
                int nl = wn * 32 + nb * 8 + t * 2;
                float p0 = ph_s[nl], v0 = v_s[nl];
                float p1 = ph_s[nl + 1], v1 = v_s[nl + 1];
                rs[mb * 2 + 0] += tanh_fast(acc[mb][nb][0] + p0) * v0
                                + tanh_fast(acc[mb][nb][1] + p1) * v1;
                rs[mb * 2 + 1] += tanh_fast(acc[mb][nb][2] + p0) * v0
                                + tanh_fast(acc[mb][nb][3] + p1) * v1;
            }
        }
        #pragma unroll
        for (int i = 0; i < 4; ++i) {
            rs[i] += __shfl_xor_sync(0xffffffffu, rs[i], 1);
            rs[i] += __shfl_xor_sync(0xffffffffu, rs[i], 2);
        }
        if (t == 0) {
            atomicAdd(&score_s[wm * 32 + g], rs[0]);
            atomicAdd(&score_s[wm * 32 + g + 8], rs[1]);
            atomicAdd(&score_s[wm * 32 + 16 + g], rs[2]);
            atomicAdd(&score_s[wm * 32 + 24 + g], rs[3]);
        }
        __syncthreads();   // score_s done; stage buffers free for next chunk
    }

    if (tid < 128) atomicAdd(&g_score[m0 + tid], score_s[tid]);
}

// ---------------- softmax over S per batch ----------------
__global__ void k_softmax(float* __restrict__ out) {
    __shared__ float red[256];
    int b = blockIdx.x, tid = threadIdx.x;  // 256 threads, 8 elems each
    float v[8];
    float mx = -1e30f;
    #pragma unroll
    for (int i = 0; i < 8; ++i) {
        float x = g_score[b * Sz + tid + i * 256];
        v[i] = x;
        mx = fmaxf(mx, x);
    }
    red[tid] = mx;
    __syncthreads();
    for (int o = 128; o > 0; o >>= 1) {
        if (tid < o) red[tid] = fmaxf(red[tid], red[tid + o]);
        __syncthreads();
    }
    mx = red[0];
    __syncthreads();
    float sum = 0.f;
    #pragma unroll
    for (int i = 0; i < 8; ++i) { v[i] = expf(v[i] - mx); sum += v[i]; }
    red[tid] = sum;
    __syncthreads();
    for (int o = 128; o > 0; o >>= 1) {
        if (tid < o) red[tid] += red[tid + o];
        __syncthreads();
    }
    float tot = red[0];
    #pragma unroll
    for (int i = 0; i < 8; ++i)
        out[b * Sz + tid + i * 256] = v[i] / tot;
}

// ---------------- launch ----------------
extern "C" void kernel_launch(void* const* d_in, const int* in_sizes, int n_in,
                              void* d_out, int out_size) {
    const float* enc = (const float*)d_in[0];   // [B,S,H]
    const float* lh  = (const float*)d_in[1];   // [B,H]
    const float* W1  = (const float*)d_in[2];   // [H,U]
    const float* W1b = (const float*)d_in[3];   // [U]
    const float* W2  = (const float*)d_in[4];   // [H,U]
    const float* W2b = (const float*)d_in[5];   // [U]
    const float* Vw  = (const float*)d_in[6];   // [U,1]
    float* out = (float*)d_out;                  // [B,S,1]

    cudaFuncSetAttribute(k_main, cudaFuncAttributeMaxDynamicSharedMemorySize, SMEM_MAIN);

    k_convert_x<<<2048, 256>>>(enc);
    k_convert_w1<<<dim3(32, 32), dim3(32, 8)>>>(W1);
    k_init_ph<<<128, 256>>>(W1b, W2b);
    k_ph<<<dim3(8, 32), 256>>>(lh, W2);
    k_main<<<dim3(512, 2), 512, SMEM_MAIN>>>(Vw);
    k_softmax<<<Bz, 256>>>(out);
}

// round 8
// speedup vs baseline: 1.1672x; 1.1672x over previous
#include <cuda_runtime.h>
#include <cuda_fp16.h>
#include <cstdint>
#include <cstddef>

// Problem constants
#define Bz 32
#define Sz 2048
#define Hz 1024
#define Uz 1024
#define MTOT 65536   // B*S

// Scratch (device globals — no runtime allocation)
__device__ __align__(128) __half g_W1h[Uz * Hz];          // W1^T: [u][h] fp16
__device__ __align__(128) __half g_Xh[(size_t)MTOT * Hz]; // X fp16: [m][h]
__device__ float g_ph[Bz * Uz];                            // W1_b + W2_b + h @ W2
__device__ float g_score[MTOT];                            // pre-softmax scores

// ---------------- PTX helpers (baseline compute_103 only) ----------------
__device__ __forceinline__ uint32_t smem_u32(const void* p) {
    uint32_t a;
    asm("{ .reg .u64 t; cvta.to.shared.u64 t, %1; cvt.u32.u64 %0, t; }" : "=r"(a) : "l"(p));
    return a;
}

#define LDSM_X4(r0, r1, r2, r3, addr)                                        \
    asm volatile("ldmatrix.sync.aligned.m8n8.x4.shared.b16 {%0,%1,%2,%3}, [%4];" \
        : "=r"(r0), "=r"(r1), "=r"(r2), "=r"(r3) : "r"(addr))

#define MMA16816(c, a, b0v, b1v)                                             \
    asm volatile("mma.sync.aligned.m16n8k16.row.col.f32.f16.f16.f32 "        \
        "{%0,%1,%2,%3}, {%4,%5,%6,%7}, {%8,%9}, {%0,%1,%2,%3};"              \
        : "+f"((c)[0]), "+f"((c)[1]), "+f"((c)[2]), "+f"((c)[3])             \
        : "r"((a)[0]), "r"((a)[1]), "r"((a)[2]), "r"((a)[3]),                \
          "r"(b0v), "r"(b1v))

__device__ __forceinline__ uint32_t sw128(uint32_t off) {
    return off ^ ((off >> 3) & 0x70);
}

// fast accurate-enough tanh
__device__ __forceinline__ float tanh_fast(float x) {
    x = fminf(fmaxf(x, -15.f), 15.f);
    float e = __expf(2.f * x);
    return __fdividef(e - 1.f, e + 1.f);
}

// ---------------- prep kernels ----------------
// X fp32 -> fp16 streaming convert (row layout preserved)
__global__ void __launch_bounds__(256)
k_convert_x(const float* __restrict__ X) {
    size_t i = (size_t)blockIdx.x * 256 + threadIdx.x;   // float4 index
    const size_t stride = (size_t)gridDim.x * 256;
    const size_t total = (size_t)MTOT * Hz / 4;
    for (; i < total; i += stride) {
        float4 v = *reinterpret_cast<const float4*>(X + i * 4);
        __half2 h0 = __floats2half2_rn(v.x, v.y);
        __half2 h1 = __floats2half2_rn(v.z, v.w);
        uint2 pk = make_uint2(*reinterpret_cast<uint32_t*>(&h0),
                              *reinterpret_cast<uint32_t*>(&h1));
        *reinterpret_cast<uint2*>(g_Xh + i * 4) = pk;
    }
}

// Transpose + convert W1 [H,U] fp32 -> g_W1h [U,H] fp16
__global__ void k_convert_w1(const float* __restrict__ W1) {
    __shared__ float t[32][33];
    int u0 = blockIdx.x * 32, h0 = blockIdx.y * 32;
    int tx = threadIdx.x, ty = threadIdx.y;  // 32 x 8
    #pragma unroll
    for (int j = 0; j < 32; j += 8)
        t[ty + j][tx] = W1[(size_t)(h0 + ty + j) * Uz + u0 + tx];
    __syncthreads();
    #pragma unroll
    for (int j = 0; j < 32; j += 8)
        g_W1h[(size_t)(u0 + ty + j) * Hz + h0 + tx] = __float2half(t[tx][ty + j]);
}

// ph[b][u] = W1_b[u] + W2_b[u]; also zero g_score
__global__ void k_init_ph(const float* __restrict__ W1b, const float* __restrict__ W2b) {
    int i = blockIdx.x * 256 + threadIdx.x;  // 32768 total
    int u = i & (Uz - 1);
    g_ph[i] = W1b[u] + W2b[u];
    g_score[i] = 0.f;
    g_score[i + 32768] = 0.f;
}

// ph[b][u] += sum_h lh[b][h] * W2[h][u]   (h-slices of 32 for grid width)
__global__ void k_ph(const float* __restrict__ lh, const float* __restrict__ W2) {
    __shared__ float lh_s[32][32];
    int u0 = blockIdx.x * 128, h0 = blockIdx.y * 32;
    int tid = threadIdx.x;
    for (int idx = tid; idx < 1024; idx += 256) {
        int bb = idx >> 5, hh = idx & 31;
        lh_s[bb][hh] = lh[bb * Hz + h0 + hh];
    }
    __syncthreads();
    int u = u0 + (tid & 127);
    int bh = (tid >> 7) * 16;
    float acc[16];
    #pragma unroll
    for (int i = 0; i < 16; ++i) acc[i] = 0.f;
    for (int hh = 0; hh < 32; ++hh) {
        float w = W2[(size_t)(h0 + hh) * Uz + u];
        #pragma unroll
        for (int i = 0; i < 16; ++i) acc[i] += lh_s[bh + i][hh] * w;
    }
    #pragma unroll
    for (int i = 0; i < 16; ++i) atomicAdd(&g_ph[(bh + i) * Uz + u], acc[i]);
}

// ---------------- fused main: GEMM(HMMA) + tanh + V-dot ----------------
// Grid (4, 512): blockIdx.x = n-quarter (256 cols), blockIdx.y = m-tile (128).
// y-major launch keeps same-m CTAs concurrent -> X tiles 4x-shared in L2.
// 256 threads / 8 warps, warp grid (2m, 4n), warp tile 64(m) x 64(n).
// K = 1024 in 16 slices of 64, 4-stage cp.async pipeline.
// SMEM map (bytes):
//   [0   .. 512)     score_s (128 f32)
//   [512 .. 1536)    ph_s    (256 f32)
//   [1536.. 2560)    v_s     (256 f32)
//   [2560.. 68096)   X fp16  4 stages x [128 x 64] SW128 (16KB/stage)
//   [68096..199168)  W fp16  4 stages x [256 x 64] SW128 (32KB/stage)
#define SMEM_MAIN 199168

__global__ void __launch_bounds__(256, 1)
k_main(const float* __restrict__ Vw) {
    extern __shared__ char smem[];
    const uint32_t sb = smem_u32(smem);
    float* score_s = reinterpret_cast<float*>(smem);
    float* ph_s = reinterpret_cast<float*>(smem + 512);
    float* v_s = reinterpret_cast<float*>(smem + 1536);
    const uint32_t XS = sb + 2560;
    const uint32_t WS = sb + 68096;

    const int tid = threadIdx.x;
    const int wid = tid >> 5, l = tid & 31;
    const int wm = wid & 1, wn = wid >> 1;     // 2m x 4n warp grid
    const int m0 = blockIdx.y * 128;
    const int n0 = blockIdx.x * 256;
    const int b = m0 >> 11;                    // batch (2048 rows each)

    if (tid < 128) score_s[tid] = 0.f;
    ph_s[tid] = g_ph[b * Uz + n0 + tid];
    v_s[tid] = Vw[n0 + tid];

    // ldmatrix lane-invariant offset pieces
    const uint32_t a_row = (uint32_t)(wm * 64 + (l & 15));
    const uint32_t a_k16 = (uint32_t)(((l >> 4) & 1) * 16);
    const uint32_t b_row = (uint32_t)(wn * 64 + ((l >> 4) & 1) * 8 + (l & 7));
    const uint32_t b_k16 = (uint32_t)(((l >> 3) & 1) * 16);

    // cp.async pieces: X 1024 chunks + W 2048 chunks of 16B, 256 threads
    const int cp_r = tid >> 3;            // row 0..31 base
    const int cp_c = tid & 7;             // 16B column 0..7

    float acc[4][8][4];
    #pragma unroll
    for (int mb = 0; mb < 4; ++mb)
        #pragma unroll
        for (int nb = 0; nb < 8; ++nb)
            #pragma unroll
            for (int i = 0; i < 4; ++i) acc[mb][nb][i] = 0.f;

    // ---- issue cp.async loads for slice s into stage s&3 ----
    auto load_slice = [&](int s) {
        const int st = s & 3;
        const int k0 = s * 64;
        const uint32_t xdst = XS + st * 16384;
        const uint32_t wdst = WS + st * 32768;
        const __half* xsrc = g_Xh + (size_t)m0 * Hz + k0;
        const __half* wsrc = g_W1h + (size_t)n0 * Hz + k0;
        #pragma unroll
        for (int i = 0; i < 4; ++i) {         // X: 128 rows
            int r = cp_r + i * 32;
            uint32_t dso = sw128((uint32_t)(r * 128 + cp_c * 16));
            size_t gx = __cvta_generic_to_global(xsrc + (size_t)r * Hz + cp_c * 8);
            asm volatile("cp.async.cg.shared.global [%0], [%1], 16;"
                         :: "r"(xdst + dso), "l"(gx));
        }
        #pragma unroll
        for (int i = 0; i < 8; ++i) {         // W: 256 rows
            int r = cp_r + i * 32;
            uint32_t dso = sw128((uint32_t)(r * 128 + cp_c * 16));
            size_t gw = __cvta_generic_to_global(wsrc + (size_t)r * Hz + cp_c * 8);
            asm volatile("cp.async.cg.shared.global [%0], [%1], 16;"
                         :: "r"(wdst + dso), "l"(gw));
        }
        asm volatile("cp.async.commit_group;");
    };

    // prologue: fill 3 stages
    load_slice(0);
    load_slice(1);
    load_slice(2);

    for (int s = 0; s < 16; ++s) {
        if (s < 14)      asm volatile("cp.async.wait_group 2;");
        else if (s < 15) asm volatile("cp.async.wait_group 1;");
        else             asm volatile("cp.async.wait_group 0;");
        __syncthreads();   // publish stage s; stage (s+3)&3 free

        if (s + 3 < 16) load_slice(s + 3);

        const uint32_t xb = XS + (s & 3) * 16384;
        const uint32_t wb = WS + (s & 3) * 32768;

        #pragma unroll
        for (int kk = 0; kk < 4; ++kk) {      // four k16 steps per 64-k slice
            uint32_t fa[4][4], fb[4][4];
            #pragma unroll
            for (int mb = 0; mb < 4; ++mb) {
                uint32_t off = (a_row + mb * 16) * 128 + kk * 32 + a_k16;
                LDSM_X4(fa[mb][0], fa[mb][1], fa[mb][2], fa[mb][3],
                        xb + sw128(off));
            }
            #pragma unroll
            for (int p = 0; p < 4; ++p) {
                uint32_t off = (b_row + p * 16) * 128 + kk * 32 + b_k16;
                LDSM_X4(fb[p][0], fb[p][1], fb[p][2], fb[p][3],
                        wb + sw128(off));
            }
            #pragma unroll
            for (int mb = 0; mb < 4; ++mb)
                #pragma unroll
                for (int nb = 0; nb < 8; ++nb)
                    MMA16816(acc[mb][nb], fa[mb],
                             fb[nb >> 1][(nb & 1) * 2],
                             fb[nb >> 1][(nb & 1) * 2 + 1]);
        }
    }

    // ---- epilogue: tanh(acc + ph) * v, reduce over the 256 n-cols ----
    const int t = l & 3, g = l >> 2;
    #pragma unroll
    for (int mb = 0; mb < 4; ++mb) {
        float rs0 = 0.f, rs1 = 0.f;
        #pragma unroll
        for (int nb = 0; nb < 8; ++nb) {
            int nl = wn * 64 + nb * 8 + t * 2;
            float p0 = ph_s[nl], v0 = v_s[nl];
            float p1 = ph_s[nl + 1], v1 = v_s[nl + 1];
            rs0 += tanh_fast(acc[mb][nb][0] + p0) * v0
                 + tanh_fast(acc[mb][nb][1] + p1) * v1;
            rs1 += tanh_fast(acc[mb][nb][2] + p0) * v0
                 + tanh_fast(acc[mb][nb][3] + p1) * v1;
        }
        rs0 += __shfl_xor_sync(0xffffffffu, rs0, 1);
        rs0 += __shfl_xor_sync(0xffffffffu, rs0, 2);
        rs1 += __shfl_xor_sync(0xffffffffu, rs1, 1);
        rs1 += __shfl_xor_sync(0xffffffffu, rs1, 2);
        if (t == 0) {
            int r0 = wm * 64 + mb * 16 + g;
            atomicAdd(&score_s[r0], rs0);
            atomicAdd(&score_s[r0 + 8], rs1);
        }
    }
    __syncthreads();

    if (tid < 128) atomicAdd(&g_score[m0 + tid], score_s[tid]);
}

// ---------------- softmax over S per batch ----------------
__global__ void k_softmax(float* __restrict__ out) {
    __shared__ float red[256];
    int b = blockIdx.x, tid = threadIdx.x;  // 256 threads, 8 elems each
    float v[8];
    float mx = -1e30f;
    #pragma unroll
    for (int i = 0; i < 8; ++i) {
        float x = g_score[b * Sz + tid + i * 256];
        v[i] = x;
        mx = fmaxf(mx, x);
    }
    red[tid] = mx;
    __syncthreads();
    for (int o = 128; o > 0; o >>= 1) {
        if (tid < o) red[tid] = fmaxf(red[tid], red[tid + o]);
        __syncthreads();
    }
    mx = red[0];
    __syncthreads();
    float sum = 0.f;
    #pragma unroll
    for (int i = 0; i < 8; ++i) { v[i] = expf(v[i] - mx); sum += v[i]; }
    red[tid] = sum;
    __syncthreads();
    for (int o = 128; o > 0; o >>= 1) {
        if (tid < o) red[tid] += red[tid + o];
        __syncthreads();
    }
    float tot = red[0];
    #pragma unroll
    for (int i = 0; i < 8; ++i)
        out[b * Sz + tid + i * 256] = v[i] / tot;
}

// ---------------- launch ----------------
extern "C" void kernel_launch(void* const* d_in, const int* in_sizes, int n_in,
                              void* d_out, int out_size) {
    const float* enc = (const float*)d_in[0];   // [B,S,H]
    const float* lh  = (const float*)d_in[1];   // [B,H]
    const float* W1  = (const float*)d_in[2];   // [H,U]
    const float* W1b = (const float*)d_in[3];   // [U]
    const float* W2  = (const float*)d_in[4];   // [H,U]
    const float* W2b = (const float*)d_in[5];   // [U]
    const float* Vw  = (const float*)d_in[6];   // [U,1]
    float* out = (float*)d_out;                  // [B,S,1]

    cudaFuncSetAttribute(k_main, cudaFuncAttributeMaxDynamicSharedMemorySize, SMEM_MAIN);

    k_convert_x<<<2048, 256>>>(enc);
    k_convert_w1<<<dim3(32, 32), dim3(32, 8)>>>(W1);
    k_init_ph<<<128, 256>>>(W1b, W2b);
    k_ph<<<dim3(8, 32), 256>>>(lh, W2);
    k_main<<<dim3(4, 512), 256, SMEM_MAIN>>>(Vw);
    k_softmax<<<Bz, 256>>>(out);
}

// round 9
// speedup vs baseline: 1.1798x; 1.0108x over previous
#include <cuda_runtime.h>
#include <cuda_fp16.h>
#include <cstdint>
#include <cstddef>

// Problem constants
#define Bz 32
#define Sz 2048
#define Hz 1024
#define Uz 1024
#define MTOT 65536   // B*S

// Scratch (device globals — no runtime allocation)
__device__ __align__(128) __half g_W1h[Uz * Hz];          // W1^T: [u][h] fp16
__device__ __align__(128) __half g_Xh[(size_t)MTOT * Hz]; // X fp16: [m][h]
__device__ float g_ph[Bz * Uz];                            // W1_b + W2_b + h @ W2
__device__ float g_score[MTOT];                            // pre-softmax scores

// ---------------- PTX helpers (baseline compute_103 only) ----------------
__device__ __forceinline__ uint32_t smem_u32(const void* p) {
    uint32_t a;
    asm("{ .reg .u64 t; cvta.to.shared.u64 t, %1; cvt.u32.u64 %0, t; }" : "=r"(a) : "l"(p));
    return a;
}

#define LDSM_X4(r0, r1, r2, r3, addr)                                        \
    asm volatile("ldmatrix.sync.aligned.m8n8.x4.shared.b16 {%0,%1,%2,%3}, [%4];" \
        : "=r"(r0), "=r"(r1), "=r"(r2), "=r"(r3) : "r"(addr))

#define MMA16816(c, a, b0v, b1v)                                             \
    asm volatile("mma.sync.aligned.m16n8k16.row.col.f32.f16.f16.f32 "        \
        "{%0,%1,%2,%3}, {%4,%5,%6,%7}, {%8,%9}, {%0,%1,%2,%3};"              \
        : "+f"((c)[0]), "+f"((c)[1]), "+f"((c)[2]), "+f"((c)[3])             \
        : "r"((a)[0]), "r"((a)[1]), "r"((a)[2]), "r"((a)[3]),                \
          "r"(b0v), "r"(b1v))

__device__ __forceinline__ uint32_t sw128(uint32_t off) {
    return off ^ ((off >> 3) & 0x70);
}

// fast accurate-enough tanh
__device__ __forceinline__ float tanh_fast(float x) {
    x = fminf(fmaxf(x, -15.f), 15.f);
    float e = __expf(2.f * x);
    return __fdividef(e - 1.f, e + 1.f);
}

// ---------------- prep kernels ----------------
// X fp32 -> fp16 streaming convert (row layout preserved)
__global__ void __launch_bounds__(256)
k_convert_x(const float* __restrict__ X) {
    size_t i = (size_t)blockIdx.x * 256 + threadIdx.x;   // float4 index
    const size_t stride = (size_t)gridDim.x * 256;
    const size_t total = (size_t)MTOT * Hz / 4;
    for (; i < total; i += stride) {
        float4 v = *reinterpret_cast<const float4*>(X + i * 4);
        __half2 h0 = __floats2half2_rn(v.x, v.y);
        __half2 h1 = __floats2half2_rn(v.z, v.w);
        uint2 pk = make_uint2(*reinterpret_cast<uint32_t*>(&h0),
                              *reinterpret_cast<uint32_t*>(&h1));
        *reinterpret_cast<uint2*>(g_Xh + i * 4) = pk;
    }
}

// Transpose + convert W1 [H,U] fp32 -> g_W1h [U,H] fp16
__global__ void k_convert_w1(const float* __restrict__ W1) {
    __shared__ float t[32][33];
    int u0 = blockIdx.x * 32, h0 = blockIdx.y * 32;
    int tx = threadIdx.x, ty = threadIdx.y;  // 32 x 8
    #pragma unroll
    for (int j = 0; j < 32; j += 8)
        t[ty + j][tx] = W1[(size_t)(h0 + ty + j) * Uz + u0 + tx];
    __syncthreads();
    #pragma unroll
    for (int j = 0; j < 32; j += 8)
        g_W1h[(size_t)(u0 + ty + j) * Hz + h0 + tx] = __float2half(t[tx][ty + j]);
}

// ph[b][u] = W1_b[u] + W2_b[u]; also zero g_score
__global__ void k_init_ph(const float* __restrict__ W1b, const float* __restrict__ W2b) {
    int i = blockIdx.x * 256 + threadIdx.x;  // 32768 total
    int u = i & (Uz - 1);
    g_ph[i] = W1b[u] + W2b[u];
    g_score[i] = 0.f;
    g_score[i + 32768] = 0.f;
}

// ph[b][u] += sum_h lh[b][h] * W2[h][u]   (u-blocks of 64, h-slices of 32)
__global__ void k_ph(const float* __restrict__ lh, const float* __restrict__ W2) {
    __shared__ float lh_s[32][32];
    int u0 = blockIdx.x * 64, h0 = blockIdx.y * 32;
    int tid = threadIdx.x;
    for (int idx = tid; idx < 1024; idx += 256) {
        int bb = idx >> 5, hh = idx & 31;
        lh_s[bb][hh] = lh[bb * Hz + h0 + hh];
    }
    __syncthreads();
    int u = u0 + (tid & 63);
    int bh = (tid >> 6) * 8;     // 4 groups x 8 batches
    float acc[8];
    #pragma unroll
    for (int i = 0; i < 8; ++i) acc[i] = 0.f;
    for (int hh = 0; hh < 32; ++hh) {
        float w = W2[(size_t)(h0 + hh) * Uz + u];
        #pragma unroll
        for (int i = 0; i < 8; ++i) acc[i] += lh_s[bh + i][hh] * w;
    }
    #pragma unroll
    for (int i = 0; i < 8; ++i) atomicAdd(&g_ph[(bh + i) * Uz + u], acc[i]);
}

// ---------------- fused main: GEMM(HMMA) + tanh + V-dot ----------------
// Grid (4, 512): blockIdx.x = n-quarter (256 cols), blockIdx.y = m-tile (128).
// y-major launch keeps same-m CTAs concurrent -> X tiles 4x-shared in L2.
// 256 threads / 8 warps, warp grid (2m, 4n), warp tile 64(m) x 64(n).
// K = 1024 in 16 slices of 64, 4-stage cp.async pipeline, register
// double-buffered ldmatrix fragments across k16 steps.
// SMEM map (bytes):
//   [0   .. 512)     score_s (128 f32)
//   [512 .. 1536)    ph_s    (256 f32)
//   [1536.. 2560)    v_s     (256 f32)
//   [2560.. 68096)   X fp16  4 stages x [128 x 64] SW128 (16KB/stage)
//   [68096..199168)  W fp16  4 stages x [256 x 64] SW128 (32KB/stage)
#define SMEM_MAIN 199168

__global__ void __launch_bounds__(256, 1)
k_main(const float* __restrict__ Vw) {
    extern __shared__ char smem[];
    const uint32_t sb = smem_u32(smem);
    float* score_s = reinterpret_cast<float*>(smem);
    float* ph_s = reinterpret_cast<float*>(smem + 512);
    float* v_s = reinterpret_cast<float*>(smem + 1536);
    const uint32_t XS = sb + 2560;
    const uint32_t WS = sb + 68096;

    const int tid = threadIdx.x;
    const int wid = tid >> 5, l = tid & 31;
    const int wm = wid & 1, wn = wid >> 1;     // 2m x 4n warp grid
    const int m0 = blockIdx.y * 128;
    const int n0 = blockIdx.x * 256;
    const int b = m0 >> 11;                    // batch (2048 rows each)

    if (tid < 128) score_s[tid] = 0.f;
    ph_s[tid] = g_ph[b * Uz + n0 + tid];
    v_s[tid] = Vw[n0 + tid];

    // ldmatrix lane-invariant offset pieces
    const uint32_t a_row = (uint32_t)(wm * 64 + (l & 15));
    const uint32_t a_k16 = (uint32_t)(((l >> 4) & 1) * 16);
    const uint32_t b_row = (uint32_t)(wn * 64 + ((l >> 4) & 1) * 8 + (l & 7));
    const uint32_t b_k16 = (uint32_t)(((l >> 3) & 1) * 16);

    // cp.async pieces: X 1024 chunks + W 2048 chunks of 16B, 256 threads
    const int cp_r = tid >> 3;            // row 0..31 base
    const int cp_c = tid & 7;             // 16B column 0..7

    float acc[4][8][4];
    #pragma unroll
    for (int mb = 0; mb < 4; ++mb)
        #pragma unroll
        for (int nb = 0; nb < 8; ++nb)
            #pragma unroll
            for (int i = 0; i < 4; ++i) acc[mb][nb][i] = 0.f;

    // ---- issue cp.async loads for slice s into stage s&3 ----
    auto load_slice = [&](int s) {
        const int st = s & 3;
        const int k0 = s * 64;
        const uint32_t xdst = XS + st * 16384;
        const uint32_t wdst = WS + st * 32768;
        const __half* xsrc = g_Xh + (size_t)m0 * Hz + k0;
        const __half* wsrc = g_W1h + (size_t)n0 * Hz + k0;
        #pragma unroll
        for (int i = 0; i < 4; ++i) {         // X: 128 rows
            int r = cp_r + i * 32;
            uint32_t dso = sw128((uint32_t)(r * 128 + cp_c * 16));
            size_t gx = __cvta_generic_to_global(xsrc + (size_t)r * Hz + cp_c * 8);
            asm volatile("cp.async.cg.shared.global [%0], [%1], 16;"
                         :: "r"(xdst + dso), "l"(gx));
        }
        #pragma unroll
        for (int i = 0; i < 8; ++i) {         // W: 256 rows
            int r = cp_r + i * 32;
            uint32_t dso = sw128((uint32_t)(r * 128 + cp_c * 16));
            size_t gw = __cvta_generic_to_global(wsrc + (size_t)r * Hz + cp_c * 8);
            asm volatile("cp.async.cg.shared.global [%0], [%1], 16;"
                         :: "r"(wdst + dso), "l"(gw));
        }
        asm volatile("cp.async.commit_group;");
    };

    // prologue: fill 3 stages
    load_slice(0);
    load_slice(1);
    load_slice(2);

    for (int s = 0; s < 16; ++s) {
        if (s < 14)      asm volatile("cp.async.wait_group 2;");
        else if (s < 15) asm volatile("cp.async.wait_group 1;");
        else             asm volatile("cp.async.wait_group 0;");
        __syncthreads();   // publish stage s; stage (s+3)&3 free

        if (s + 3 < 16) load_slice(s + 3);

        const uint32_t xb = XS + (s & 3) * 16384;
        const uint32_t wb = WS + (s & 3) * 32768;

        // register double-buffered fragments across the 4 k16 steps
        uint32_t fa[2][4][4], fb[2][4][4];
        #pragma unroll
        for (int mb = 0; mb < 4; ++mb) {
            uint32_t off = (a_row + mb * 16) * 128 + a_k16;
            LDSM_X4(fa[0][mb][0], fa[0][mb][1], fa[0][mb][2], fa[0][mb][3],
                    xb + sw128(off));
        }
        #pragma unroll
        for (int p = 0; p < 4; ++p) {
            uint32_t off = (b_row + p * 16) * 128 + b_k16;
            LDSM_X4(fb[0][p][0], fb[0][p][1], fb[0][p][2], fb[0][p][3],
                    wb + sw128(off));
        }

        #pragma unroll
        for (int kk = 0; kk < 4; ++kk) {      // four k16 steps per 64-k slice
            const int cur = kk & 1, nxt = cur ^ 1;
            if (kk < 3) {
                #pragma unroll
                for (int mb = 0; mb < 4; ++mb) {
                    uint32_t off = (a_row + mb * 16) * 128 + (kk + 1) * 32 + a_k16;
                    LDSM_X4(fa[nxt][mb][0], fa[nxt][mb][1], fa[nxt][mb][2],
                            fa[nxt][mb][3], xb + sw128(off));
                }
                #pragma unroll
                for (int p = 0; p < 4; ++p) {
                    uint32_t off = (b_row + p * 16) * 128 + (kk + 1) * 32 + b_k16;
                    LDSM_X4(fb[nxt][p][0], fb[nxt][p][1], fb[nxt][p][2],
                            fb[nxt][p][3], wb + sw128(off));
                }
            }
            #pragma unroll
            for (int mb = 0; mb < 4; ++mb)
                #pragma unroll
                for (int nb = 0; nb < 8; ++nb)
                    MMA16816(acc[mb][nb], fa[cur][mb],
                             fb[cur][nb >> 1][(nb & 1) * 2],
                             fb[cur][nb >> 1][(nb & 1) * 2 + 1]);
        }
    }

    // ---- epilogue: tanh(acc + ph) * v, reduce over the 256 n-cols ----
    const int t = l & 3, g = l >> 2;
    #pragma unroll
    for (int mb = 0; mb < 4; ++mb) {
        float rs0 = 0.f, rs1 = 0.f;
        #pragma unroll
        for (int nb = 0; nb < 8; ++nb) {
            int nl = wn * 64 + nb * 8 + t * 2;
            float p0 = ph_s[nl], v0 = v_s[nl];
            float p1 = ph_s[nl + 1], v1 = v_s[nl + 1];
            rs0 += tanh_fast(acc[mb][nb][0] + p0) * v0
                 + tanh_fast(acc[mb][nb][1] + p1) * v1;
            rs1 += tanh_fast(acc[mb][nb][2] + p0) * v0
                 + tanh_fast(acc[mb][nb][3] + p1) * v1;
        }
        rs0 += __shfl_xor_sync(0xffffffffu, rs0, 1);
        rs0 += __shfl_xor_sync(0xffffffffu, rs0, 2);
        rs1 += __shfl_xor_sync(0xffffffffu, rs1, 1);
        rs1 += __shfl_xor_sync(0xffffffffu, rs1, 2);
        if (t == 0) {
            int r0 = wm * 64 + mb * 16 + g;
            atomicAdd(&score_s[r0], rs0);
            atomicAdd(&score_s[r0 + 8], rs1);
        }
    }
    __syncthreads();

    if (tid < 128) atomicAdd(&g_score[m0 + tid], score_s[tid]);
}

// ---------------- softmax over S per batch ----------------
__global__ void k_softmax(float* __restrict__ out) {
    __shared__ float red[256];
    int b = blockIdx.x, tid = threadIdx.x;  // 256 threads, 8 elems each
    float v[8];
    float mx = -1e30f;
    #pragma unroll
    for (int i = 0; i < 8; ++i) {
        float x = g_score[b * Sz + tid + i * 256];
        v[i] = x;
        mx = fmaxf(mx, x);
    }
    red[tid] = mx;
    __syncthreads();
    for (int o = 128; o > 0; o >>= 1) {
        if (tid < o) red[tid] = fmaxf(red[tid], red[tid + o]);
        __syncthreads();
    }
    mx = red[0];
    __syncthreads();
    float sum = 0.f;
    #pragma unroll
    for (int i = 0; i < 8; ++i) { v[i] = expf(v[i] - mx); sum += v[i]; }
    red[tid] = sum;
    __syncthreads();
    for (int o = 128; o > 0; o >>= 1) {
        if (tid < o) red[tid] += red[tid + o];
        __syncthreads();
    }
    float tot = red[0];
    #pragma unroll
    for (int i = 0; i < 8; ++i)
        out[b * Sz + tid + i * 256] = v[i] / tot;
}

// ---------------- launch ----------------
extern "C" void kernel_launch(void* const* d_in, const int* in_sizes, int n_in,
                              void* d_out, int out_size) {
    const float* enc = (const float*)d_in[0];   // [B,S,H]
    const float* lh  = (const float*)d_in[1];   // [B,H]
    const float* W1  = (const float*)d_in[2];   // [H,U]
    const float* W1b = (const float*)d_in[3];   // [U]
    const float* W2  = (const float*)d_in[4];   // [H,U]
    const float* W2b = (const float*)d_in[5];   // [U]
    const float* Vw  = (const float*)d_in[6];   // [U,1]
    float* out = (float*)d_out;                  // [B,S,1]

    cudaFuncSetAttribute(k_main, cudaFuncAttributeMaxDynamicSharedMemorySize, SMEM_MAIN);

    k_convert_x<<<2048, 256>>>(enc);
    k_convert_w1<<<dim3(32, 32), dim3(32, 8)>>>(W1);
    k_init_ph<<<128, 256>>>(W1b, W2b);
    k_ph<<<dim3(16, 32), 256>>>(lh, W2);
    k_main<<<dim3(4, 512), 256, SMEM_MAIN>>>(Vw);
    k_softmax<<<Bz, 256>>>(out);
}

// round 10
// speedup vs baseline: 1.3183x; 1.1174x over previous
#include <cuda_runtime.h>
#include <cuda_fp16.h>
#include <cstdint>
#include <cstddef>

// Problem constants
#define Bz 32
#define Sz 2048
#define Hz 1024
#define Uz 1024
#define MTOT 65536   // B*S

// Scratch (device globals — no runtime allocation)
__device__ __align__(128) __half g_W1h[Uz * Hz];          // W1^T: [u][h] fp16
__device__ __align__(128) __half g_Xh[(size_t)MTOT * Hz]; // X fp16: [m][h]
__device__ float g_ph[Bz * Uz];                            // W1_b + W2_b + h @ W2
__device__ float g_score[MTOT];                            // pre-softmax scores

// ---------------- PTX helpers (baseline compute_103 only) ----------------
__device__ __forceinline__ uint32_t smem_u32(const void* p) {
    uint32_t a;
    asm("{ .reg .u64 t; cvta.to.shared.u64 t, %1; cvt.u32.u64 %0, t; }" : "=r"(a) : "l"(p));
    return a;
}

#define LDSM_X4(r0, r1, r2, r3, addr)                                        \
    asm volatile("ldmatrix.sync.aligned.m8n8.x4.shared.b16 {%0,%1,%2,%3}, [%4];" \
        : "=r"(r0), "=r"(r1), "=r"(r2), "=r"(r3) : "r"(addr))

#define MMA16816(c, a, b0v, b1v)                                             \
    asm volatile("mma.sync.aligned.m16n8k16.row.col.f32.f16.f16.f32 "        \
        "{%0,%1,%2,%3}, {%4,%5,%6,%7}, {%8,%9}, {%0,%1,%2,%3};"              \
        : "+f"((c)[0]), "+f"((c)[1]), "+f"((c)[2]), "+f"((c)[3])             \
        : "r"((a)[0]), "r"((a)[1]), "r"((a)[2]), "r"((a)[3]),                \
          "r"(b0v), "r"(b1v))

__device__ __forceinline__ uint32_t sw128(uint32_t off) {
    return off ^ ((off >> 3) & 0x70);
}

// fast accurate-enough tanh
__device__ __forceinline__ float tanh_fast(float x) {
    x = fminf(fmaxf(x, -15.f), 15.f);
    float e = __expf(2.f * x);
    return __fdividef(e - 1.f, e + 1.f);
}

// ---------------- prep kernels ----------------
// X fp32 -> fp16 streaming convert (row layout preserved)
__global__ void __launch_bounds__(256)
k_convert_x(const float* __restrict__ X) {
    size_t i = (size_t)blockIdx.x * 256 + threadIdx.x;   // float4 index
    const size_t stride = (size_t)gridDim.x * 256;
    const size_t total = (size_t)MTOT * Hz / 4;
    for (; i < total; i += stride) {
        float4 v = *reinterpret_cast<const float4*>(X + i * 4);
        __half2 h0 = __floats2half2_rn(v.x, v.y);
        __half2 h1 = __floats2half2_rn(v.z, v.w);
        uint2 pk = make_uint2(*reinterpret_cast<uint32_t*>(&h0),
                              *reinterpret_cast<uint32_t*>(&h1));
        *reinterpret_cast<uint2*>(g_Xh + i * 4) = pk;
    }
}

// Transpose + convert W1 [H,U] fp32 -> g_W1h [U,H] fp16
__global__ void k_convert_w1(const float* __restrict__ W1) {
    __shared__ float t[32][33];
    int u0 = blockIdx.x * 32, h0 = blockIdx.y * 32;
    int tx = threadIdx.x, ty = threadIdx.y;  // 32 x 8
    #pragma unroll
    for (int j = 0; j < 32; j += 8)
        t[ty + j][tx] = W1[(size_t)(h0 + ty + j) * Uz + u0 + tx];
    __syncthreads();
    #pragma unroll
    for (int j = 0; j < 32; j += 8)
        g_W1h[(size_t)(u0 + ty + j) * Hz + h0 + tx] = __float2half(t[tx][ty + j]);
}

// ph[b][u] = W1_b[u] + W2_b[u]; also zero g_score
__global__ void k_init_ph(const float* __restrict__ W1b, const float* __restrict__ W2b) {
    int i = blockIdx.x * 256 + threadIdx.x;  // 32768 total
    int u = i & (Uz - 1);
    g_ph[i] = W1b[u] + W2b[u];
    g_score[i] = 0.f;
    g_score[i + 32768] = 0.f;
}

// ph[b][u] += sum_h lh[b][h] * W2[h][u]   (u-blocks of 64, h-slices of 32)
__global__ void k_ph(const float* __restrict__ lh, const float* __restrict__ W2) {
    __shared__ float lh_s[32][32];
    int u0 = blockIdx.x * 64, h0 = blockIdx.y * 32;
    int tid = threadIdx.x;
    for (int idx = tid; idx < 1024; idx += 256) {
        int bb = idx >> 5, hh = idx & 31;
        lh_s[bb][hh] = lh[bb * Hz + h0 + hh];
    }
    __syncthreads();
    int u = u0 + (tid & 63);
    int bh = (tid >> 6) * 8;     // 4 groups x 8 batches
    float acc[8];
    #pragma unroll
    for (int i = 0; i < 8; ++i) acc[i] = 0.f;
    for (int hh = 0; hh < 32; ++hh) {
        float w = W2[(size_t)(h0 + hh) * Uz + u];
        #pragma unroll
        for (int i = 0; i < 8; ++i) acc[i] += lh_s[bh + i][hh] * w;
    }
    #pragma unroll
    for (int i = 0; i < 8; ++i) atomicAdd(&g_ph[(bh + i) * Uz + u], acc[i]);
}

// ---------------- fused main: GEMM(HMMA) + tanh + V-dot ----------------
// Grid (8, 512): blockIdx.x = n-octant (128 cols), blockIdx.y = m-tile (128).
// 128 threads / 4 warps per CTA, warp grid (2m, 2n), warp tile 64 x 64.
// smem 100352 B -> TWO CTAs co-resident per SM: while one CTA barriers /
// runs its epilogue, the other's MMAs keep the tensor pipe busy.
// K = 1024 in 16 slices of 64, 3-stage cp.async pipeline.
// SMEM map (bytes):
//   [0   .. 512)     score_s (128 f32)
//   [512 .. 1024)    ph_s    (128 f32)
//   [1024.. 1536)    v_s     (128 f32)
//   [2048.. 51200)   X fp16  3 stages x [128 x 64] SW128 (16KB/stage)
//   [51200..100352)  W fp16  3 stages x [128 x 64] SW128 (16KB/stage)
#define SMEM_MAIN 100352

__global__ void __launch_bounds__(128, 2)
k_main(const float* __restrict__ Vw) {
    extern __shared__ char smem[];
    const uint32_t sb = smem_u32(smem);
    float* score_s = reinterpret_cast<float*>(smem);
    float* ph_s = reinterpret_cast<float*>(smem + 512);
    float* v_s = reinterpret_cast<float*>(smem + 1024);
    const uint32_t XS = sb + 2048;
    const uint32_t WS = sb + 51200;

    const int tid = threadIdx.x;
    const int wid = tid >> 5, l = tid & 31;
    const int wm = wid & 1, wn = wid >> 1;     // 2m x 2n warp grid
    const int m0 = blockIdx.y * 128;
    const int n0 = blockIdx.x * 128;
    const int b = m0 >> 11;                    // batch (2048 rows each)

    score_s[tid] = 0.f;
    ph_s[tid] = g_ph[b * Uz + n0 + tid];
    v_s[tid] = Vw[n0 + tid];

    // ldmatrix lane-invariant offset pieces
    const uint32_t a_row = (uint32_t)(wm * 64 + (l & 15));
    const uint32_t a_k16 = (uint32_t)(((l >> 4) & 1) * 16);
    const uint32_t b_row = (uint32_t)(wn * 64 + ((l >> 4) & 1) * 8 + (l & 7));
    const uint32_t b_k16 = (uint32_t)(((l >> 3) & 1) * 16);

    // cp.async pieces: X 1024 + W 1024 chunks of 16B, 128 threads
    const int cp_r = tid >> 3;            // row 0..15 base
    const int cp_c = tid & 7;             // 16B column 0..7

    float acc[4][8][4];
    #pragma unroll
    for (int mb = 0; mb < 4; ++mb)
        #pragma unroll
        for (int nb = 0; nb < 8; ++nb)
            #pragma unroll
            for (int i = 0; i < 4; ++i) acc[mb][nb][i] = 0.f;

    // ---- issue cp.async loads for slice s into stage s%3 ----
    auto load_slice = [&](int s) {
        const int st = s % 3;
        const int k0 = s * 64;
        const uint32_t xdst = XS + st * 16384;
        const uint32_t wdst = WS + st * 16384;
        const __half* xsrc = g_Xh + (size_t)m0 * Hz + k0;
        const __half* wsrc = g_W1h + (size_t)n0 * Hz + k0;
        #pragma unroll
        for (int i = 0; i < 8; ++i) {         // 128 rows each, 16 per pass
            int r = cp_r + i * 16;
            uint32_t dso = sw128((uint32_t)(r * 128 + cp_c * 16));
            size_t gx = __cvta_generic_to_global(xsrc + (size_t)r * Hz + cp_c * 8);
            size_t gw = __cvta_generic_to_global(wsrc + (size_t)r * Hz + cp_c * 8);
            asm volatile("cp.async.cg.shared.global [%0], [%1], 16;"
                         :: "r"(xdst + dso), "l"(gx));
            asm volatile("cp.async.cg.shared.global [%0], [%1], 16;"
                         :: "r"(wdst + dso), "l"(gw));
        }
        asm volatile("cp.async.commit_group;");
    };

    // prologue: fill 2 of 3 stages
    load_slice(0);
    load_slice(1);

    for (int s = 0; s < 16; ++s) {
        if (s < 15) asm volatile("cp.async.wait_group 1;");
        else        asm volatile("cp.async.wait_group 0;");
        __syncthreads();   // publish stage s; stage (s+2)%3 free

        if (s + 2 < 16) load_slice(s + 2);

        const uint32_t xb = XS + (s % 3) * 16384;
        const uint32_t wb = WS + (s % 3) * 16384;

        #pragma unroll
        for (int kk = 0; kk < 4; ++kk) {      // four k16 steps per 64-k slice
            uint32_t fa[4][4], fb[4][4];
            #pragma unroll
            for (int mb = 0; mb < 4; ++mb) {
                uint32_t off = (a_row + mb * 16) * 128 + kk * 32 + a_k16;
                LDSM_X4(fa[mb][0], fa[mb][1], fa[mb][2], fa[mb][3],
                        xb + sw128(off));
            }
            #pragma unroll
            for (int p = 0; p < 4; ++p) {
                uint32_t off = (b_row + p * 16) * 128 + kk * 32 + b_k16;
                LDSM_X4(fb[p][0], fb[p][1], fb[p][2], fb[p][3],
                        wb + sw128(off));
            }
            #pragma unroll
            for (int mb = 0; mb < 4; ++mb)
                #pragma unroll
                for (int nb = 0; nb < 8; ++nb)
                    MMA16816(acc[mb][nb], fa[mb],
                             fb[nb >> 1][(nb & 1) * 2],
                             fb[nb >> 1][(nb & 1) * 2 + 1]);
        }
    }

    // ---- epilogue: tanh(acc + ph) * v, reduce over the 128 n-cols ----
    const int t = l & 3, g = l >> 2;
    #pragma unroll
    for (int mb = 0; mb < 4; ++mb) {
        float rs0 = 0.f, rs1 = 0.f;
        #pragma unroll
        for (int nb = 0; nb < 8; ++nb) {
            int nl = wn * 64 + nb * 8 + t * 2;
            float p0 = ph_s[nl], v0 = v_s[nl];
            float p1 = ph_s[nl + 1], v1 = v_s[nl + 1];
            rs0 += tanh_fast(acc[mb][nb][0] + p0) * v0
                 + tanh_fast(acc[mb][nb][1] + p1) * v1;
            rs1 += tanh_fast(acc[mb][nb][2] + p0) * v0
                 + tanh_fast(acc[mb][nb][3] + p1) * v1;
        }
        rs0 += __shfl_xor_sync(0xffffffffu, rs0, 1);
        rs0 += __shfl_xor_sync(0xffffffffu, rs0, 2);
        rs1 += __shfl_xor_sync(0xffffffffu, rs1, 1);
        rs1 += __shfl_xor_sync(0xffffffffu, rs1, 2);
        if (t == 0) {
            int r0 = wm * 64 + mb * 16 + g;
            atomicAdd(&score_s[r0], rs0);
            atomicAdd(&score_s[r0 + 8], rs1);
        }
    }
    __syncthreads();

    atomicAdd(&g_score[m0 + tid], score_s[tid]);
}

// ---------------- softmax over S per batch ----------------
__global__ void k_softmax(float* __restrict__ out) {
    __shared__ float red[256];
    int b = blockIdx.x, tid = threadIdx.x;  // 256 threads, 8 elems each
    float v[8];
    float mx = -1e30f;
    #pragma unroll
    for (int i = 0; i < 8; ++i) {
        float x = g_score[b * Sz + tid + i * 256];
        v[i] = x;
        mx = fmaxf(mx, x);
    }
    red[tid] = mx;
    __syncthreads();
    for (int o = 128; o > 0; o >>= 1) {
        if (tid < o) red[tid] = fmaxf(red[tid], red[tid + o]);
        __syncthreads();
    }
    mx = red[0];
    __syncthreads();
    float sum = 0.f;
    #pragma unroll
    for (int i = 0; i < 8; ++i) { v[i] = expf(v[i] - mx); sum += v[i]; }
    red[tid] = sum;
    __syncthreads();
    for (int o = 128; o > 0; o >>= 1) {
        if (tid < o) red[tid] += red[tid + o];
        __syncthreads();
    }
    float tot = red[0];
    #pragma unroll
    for (int i = 0; i < 8; ++i)
        out[b * Sz + tid + i * 256] = v[i] / tot;
}

// ---------------- launch ----------------
extern "C" void kernel_launch(void* const* d_in, const int* in_sizes, int n_in,
                              void* d_out, int out_size) {
    const float* enc = (const float*)d_in[0];   // [B,S,H]
    const float* lh  = (const float*)d_in[1];   // [B,H]
    const float* W1  = (const float*)d_in[2];   // [H,U]
    const float* W1b = (const float*)d_in[3];   // [U]
    const float* W2  = (const float*)d_in[4];   // [H,U]
    const float* W2b = (const float*)d_in[5];   // [U]
    const float* Vw  = (const float*)d_in[6];   // [U,1]
    float* out = (float*)d_out;                  // [B,S,1]

    cudaFuncSetAttribute(k_main, cudaFuncAttributeMaxDynamicSharedMemorySize, SMEM_MAIN);

    k_convert_x<<<2048, 256>>>(enc);
    k_convert_w1<<<dim3(32, 32), dim3(32, 8)>>>(W1);
    k_init_ph<<<128, 256>>>(W1b, W2b);
    k_ph<<<dim3(16, 32), 256>>>(lh, W2);
    k_main<<<dim3(8, 512), 128, SMEM_MAIN>>>(Vw);
    k_softmax<<<Bz, 256>>>(out);
}